// round 2
// baseline (speedup 1.0000x reference)
#include <cuda_runtime.h>

// Folded circuit constants: A[4] = cos(alpha_w)*cos(beta_w), B[4] = -sin(beta_w), Wf[4]
__device__ __align__(16) float g_qc[12];

__global__ void precompute_kernel(const float* __restrict__ params,
                                  const float* __restrict__ W) {
    int w = threadIdx.x;
    if (w < 4) {
        float a = params[3 * w + 0];
        float b = params[3 * w + 1];
        // params[3w+2] (Rz) does not affect Z-expvals: Rz is diagonal-phase.
        g_qc[w]     = cosf(a) * cosf(b);   // A_w
        g_qc[4 + w] = -sinf(b);            // B_w
        g_qc[8 + w] = W[w];                // W row (Linear 4->1, no bias)
    }
}

// One thread computes 2 horizontally-adjacent 2x2 patches.
// Total threads: 8192 * 14 * 7 = 802816 = 3136 * 256 (exact).
__global__ void __launch_bounds__(256)
quanv_kernel(const float* __restrict__ x, float* __restrict__ out) {
    int t  = blockIdx.x * 256 + threadIdx.x;
    int jj = t % 7;          // pair-of-patches column index (covers j = 2*jj, 2*jj+1)
    int bi = t / 7;          // b*14 + i
    int i  = bi % 14;        // patch row
    int b  = bi / 14;        // image

    // x is (B,1,28,28) f32. Row 2i chunk [4jj .. 4jj+3] and row 2i+1 chunk, both 16B-aligned:
    // float offset row0 = b*784 + 56*i + 4*jj  -> float4 index b*196 + 14*i + jj
    const float4* xr = reinterpret_cast<const float4*>(x);
    int o0 = b * 196 + i * 14 + jj;
    float4 r0 = xr[o0];       // row 2i   : theta for (dr=0, dc=0..3)
    float4 r1 = xr[o0 + 7];   // row 2i+1 : theta for (dr=1, dc=0..3)

    const float4* qc = reinterpret_cast<const float4*>(g_qc);
    float4 Av = qc[0];        // A0..A3
    float4 Bv = qc[1];        // B0..B3
    float4 Wv = qc[2];        // W0..W3

    float s, c;
    // ---- patch 0: pixels (r0.x, r0.y, r1.x, r1.y) -> qubits 0..3 ----
    __sincosf(r0.x, &s, &c); float d0 = fmaf(Av.x, c, Bv.x * s);
    __sincosf(r0.y, &s, &c); float d1 = fmaf(Av.y, c, Bv.y * s);
    __sincosf(r1.x, &s, &c); float d2 = fmaf(Av.z, c, Bv.z * s);
    __sincosf(r1.y, &s, &c); float d3 = fmaf(Av.w, c, Bv.w * s);
    // out = W0*d0 + W1*d0*d1 + W2*d0*d1*d2 + W3*d0*d1*d2*d3 (Horner)
    float res0 = d0 * fmaf(d1, fmaf(d2, fmaf(d3, Wv.w, Wv.z), Wv.y), Wv.x);

    // ---- patch 1: pixels (r0.z, r0.w, r1.z, r1.w) ----
    __sincosf(r0.z, &s, &c); float e0 = fmaf(Av.x, c, Bv.x * s);
    __sincosf(r0.w, &s, &c); float e1 = fmaf(Av.y, c, Bv.y * s);
    __sincosf(r1.z, &s, &c); float e2 = fmaf(Av.z, c, Bv.z * s);
    __sincosf(r1.w, &s, &c); float e3 = fmaf(Av.w, c, Bv.w * s);
    float res1 = e0 * fmaf(e1, fmaf(e2, fmaf(e3, Wv.w, Wv.z), Wv.y), Wv.x);

    // out[b][i*14 + 2*jj .. +1], float offset b*196 + 14*i + 2*jj (even -> 8B aligned)
    float2 o;
    o.x = res0;
    o.y = res1;
    reinterpret_cast<float2*>(out)[b * 98 + i * 7 + jj] = o;
}

extern "C" void kernel_launch(void* const* d_in, const int* in_sizes, int n_in,
                              void* d_out, int out_size) {
    const float* x      = (const float*)d_in[0];
    const float* params = (const float*)d_in[1];
    const float* W      = (const float*)d_in[2];
    float* out          = (float*)d_out;

    precompute_kernel<<<1, 4>>>(params, W);
    quanv_kernel<<<3136, 256>>>(x, out);
}

// round 3
// speedup vs baseline: 2.9778x; 2.9778x over previous
#include <cuda_runtime.h>

__device__ __forceinline__ float patch_ev(float t0, float t1, float t2, float t3,
                                          float4 A, float4 B, float4 Wv) {
    float s, c;
    __sincosf(t0, &s, &c); float d0 = fmaf(A.x, c, B.x * s);
    __sincosf(t1, &s, &c); float d1 = fmaf(A.y, c, B.y * s);
    __sincosf(t2, &s, &c); float d2 = fmaf(A.z, c, B.z * s);
    __sincosf(t3, &s, &c); float d3 = fmaf(A.w, c, B.w * s);
    // W0*d0 + W1*d0*d1 + W2*d0*d1*d2 + W3*d0*d1*d2*d3 (Horner)
    return d0 * fmaf(d1, fmaf(d2, fmaf(d3, Wv.w, Wv.z), Wv.y), Wv.x);
}

// One thread computes 4 patches: pair (j=2jj, 2jj+1) at patch-row i AND at patch-row i+7.
// Threads: 8192 * 7 * 7 = 401408 = 1568 * 256 (exact, no bounds check).
__global__ void __launch_bounds__(256)
quanv_kernel(const float* __restrict__ x, const float* __restrict__ params,
             const float* __restrict__ W, float* __restrict__ out) {
    __shared__ __align__(16) float sqc[12];   // A0..3, B0..3, W0..3

    if (threadIdx.x < 4) {
        int w = threadIdx.x;
        float a = params[3 * w + 0];
        float b = params[3 * w + 1];
        // params[3w+2] (Rz) is diagonal-phase: no effect on Z expvals.
        sqc[w]     = cosf(a) * cosf(b);   // A_w
        sqc[4 + w] = -sinf(b);            // B_w
        sqc[8 + w] = W[w];
    }
    __syncthreads();

    int t  = blockIdx.x * 256 + threadIdx.x;
    int jj = t % 7;           // pair-of-patches column (j = 2jj, 2jj+1)
    int bi = t / 7;
    int i  = bi % 7;          // patch row in [0,7); also handles i+7
    int b  = bi / 7;          // image

    // x (B,1,28,28) f32: float4 row-chunk index = b*196 + (2i)*14/... = b*196 + i*14 + jj
    const float4* xr = reinterpret_cast<const float4*>(x);
    int o0 = b * 196 + i * 14 + jj;
    // 4 independent loads, front-batched for MLP
    float4 r0 = xr[o0];         // rows 2i
    float4 r1 = xr[o0 + 7];     // row 2i+1
    float4 r2 = xr[o0 + 98];    // row 2(i+7)
    float4 r3 = xr[o0 + 105];   // row 2(i+7)+1

    const float4* qc = reinterpret_cast<const float4*>(sqc);
    float4 Av = qc[0], Bv = qc[1], Wv = qc[2];

    float2 oA, oB;
    oA.x = patch_ev(r0.x, r0.y, r1.x, r1.y, Av, Bv, Wv);
    oA.y = patch_ev(r0.z, r0.w, r1.z, r1.w, Av, Bv, Wv);
    oB.x = patch_ev(r2.x, r2.y, r3.x, r3.y, Av, Bv, Wv);
    oB.y = patch_ev(r2.z, r2.w, r3.z, r3.w, Av, Bv, Wv);

    // out (B,196): float2 index b*98 + i*7 + jj  (and +49 for row i+7)
    float2* o2 = reinterpret_cast<float2*>(out);
    int q0 = b * 98 + i * 7 + jj;
    o2[q0]      = oA;
    o2[q0 + 49] = oB;
}

extern "C" void kernel_launch(void* const* d_in, const int* in_sizes, int n_in,
                              void* d_out, int out_size) {
    const float* x      = (const float*)d_in[0];
    const float* params = (const float*)d_in[1];
    const float* W      = (const float*)d_in[2];
    float* out          = (float*)d_out;

    quanv_kernel<<<1568, 256>>>(x, params, W, out);
}